// round 15
// baseline (speedup 1.0000x reference)
#include <cuda_runtime.h>
#include <math.h>
#include <stdint.h>

// Problem constants
#define B_   16
#define L_   512
#define H_   1024
#define HS   64     // HEAD_SIZE
#define NH   12     // HEADS
#define INFV 1000000000000.0f

// Scratch (allocation-free rule: __device__ globals)
__device__ __align__(16) float g_qwT[B_ * HS * L_];          // [b][d][l]
__device__ __align__(16) float g_kwT[B_ * HS * L_];          // [b][d][l]
__device__ __align__(16) float g_bias[B_ * 2 * NH * L_];     // [b][j][l]

// proj smem geometry (floats): K-chunk 32, 2-stage double buffer (static smem)
#define AS_FLOATS 1152         // 32 rows * 36 pad
#define BS_FLOATS 4352         // 32 k * 136 pad
#define BS_BASE   (2 * AS_FLOATS)                 // 2304
#define POOL_FLOATS (BS_BASE + 2 * BS_FLOATS)     // 11008 floats = 44032 B (static OK)

// ---------------------------------------------------------------------------
__device__ __forceinline__ void mma_tf32(
    float& c0, float& c1, float& c2, float& c3,
    uint32_t a0, uint32_t a1, uint32_t a2, uint32_t a3,
    uint32_t b0, uint32_t b1)
{
    asm volatile(
        "mma.sync.aligned.m16n8k8.row.col.f32.tf32.tf32.f32 "
        "{%0,%1,%2,%3}, {%4,%5,%6,%7}, {%8,%9}, {%0,%1,%2,%3};"
        : "+f"(c0), "+f"(c1), "+f"(c2), "+f"(c3)
        : "r"(a0), "r"(a1), "r"(a2), "r"(a3), "r"(b0), "r"(b1));
}

__device__ __forceinline__ void cp_async16(uint32_t saddr, const void* gptr) {
    asm volatile("cp.async.cg.shared.global [%0], [%1], 16;" :: "r"(saddr), "l"(gptr));
}
#define CP_COMMIT() asm volatile("cp.async.commit_group;")

// ---------------------------------------------------------------------------
// Kernel A v8: x = inputs@W1 + b1 via TF32 MMA.
//  32(M)x128(N) tile, K-chunk 32 (32 iterations -> half the barrier convoys
//  of the measured K16 version), 2-stage double buffer in STATIC smem (44KB,
//  no cudaFuncSetAttribute / dynamic smem). Copy of stage kt+1 is issued
//  after the sync of iteration kt and overlaps the full compute phase
//  (~2000cyc >> 577cyc DRAM latency).
//  Smem: As[2][32][36] (consumer banks 4g+t, conflict-free),
//        Bs[2][32][136] (consumer banks 8t+g, conflict-free).
// grid 256, 256 threads: 8 warps = 2(M half) x 4(N 32-col slabs).
// ---------------------------------------------------------------------------
__global__ __launch_bounds__(256) void proj_kernel(
    const float* __restrict__ inp, const float* __restrict__ W1,
    const float* __restrict__ b1,  const float* __restrict__ W2,
    const float* __restrict__ b2)
{
    __shared__ __align__(16) float pool[POOL_FLOATS];  // epilogue reuses as xs[32][132]

    const int tid  = threadIdx.x;
    const int lane = tid & 31;
    const int warp = tid >> 5;
    const int wm   = warp >> 2;    // 0..1 (16-row half)
    const int wn   = warp & 3;     // 0..3 (32-col slab)
    const int g    = lane >> 2;
    const int t    = lane & 3;
    const int m0   = blockIdx.x * 32;

    const uint32_t smem_base = (uint32_t)__cvta_generic_to_shared(pool);

    // ---- cp.async assignments (per 32-K stage) ----
    // A: 32m x 32k = 256 float4; 1/thread: m=tid>>3, kq=tid&7
    const int am_ = tid >> 3, akq = tid & 7;
    const float* aG = inp + (size_t)(m0 + am_) * H_ + akq * 4;
    const uint32_t a_sts = (uint32_t)(am_ * 36 + akq * 4) * 4;
    // B: 32k x 128n = 1024 float4; 4/thread: f = tid + 256*j, k=f>>5, nq=f&31
    int bk[4], bnq[4];
    #pragma unroll
    for (int j = 0; j < 4; j++) { int f = tid + 256 * j; bk[j] = f >> 5; bnq[j] = f & 31; }
    const float* bG[4];
    uint32_t b_sts[4];
    #pragma unroll
    for (int j = 0; j < 4; j++) {
        bG[j] = W1 + (size_t)bk[j] * 128 + bnq[j] * 4;
        b_sts[j] = (uint32_t)(bk[j] * 136 + bnq[j] * 4) * 4;
    }

    // ---- consumer fragment bases (floats within a stage) ----
    const int a_base = (wm * 16 + g) * 36 + t;   // +ks*8; a1=+576(16 rows), a2=+4, a3=+580
    const int b_base = t * 136 + wn * 32 + g;    // +ks*1088; b1=+544; +nt*8

    float acc[4][4];
    #pragma unroll
    for (int nt = 0; nt < 4; nt++)
        #pragma unroll
        for (int c = 0; c < 4; c++) acc[nt][c] = 0.f;

    // ---- prologue: stage 0 into buffer 0 ----
    {
        cp_async16(smem_base + a_sts, aG);
        const uint32_t bb = smem_base + BS_BASE * 4;
        #pragma unroll
        for (int j = 0; j < 4; j++)
            cp_async16(bb + b_sts[j], bG[j]);
        CP_COMMIT();
    }

    for (int kt = 0; kt < 32; kt++) {
        asm volatile("cp.async.wait_group 0;");
        __syncthreads();   // all copies visible; all warps done with the other buffer
        if (kt + 1 < 32) {
            int sp = (kt + 1) & 1;
            cp_async16(smem_base + sp * (AS_FLOATS * 4) + a_sts, aG + (kt + 1) * 32);
            const uint32_t bb = smem_base + BS_BASE * 4 + sp * (BS_FLOATS * 4);
            #pragma unroll
            for (int j = 0; j < 4; j++)
                cp_async16(bb + b_sts[j], bG[j] + (size_t)(kt + 1) * 4096);
            CP_COMMIT();
        }
        const int s_c = kt & 1;
        const float* As = pool + s_c * AS_FLOATS;
        const float* Bs = pool + BS_BASE + s_c * BS_FLOATS;
        #pragma unroll
        for (int ks = 0; ks < 4; ks++) {
            uint32_t a0, a1, a2, a3;
            {
                int o = a_base + ks * 8;
                a0 = __float_as_uint(As[o]);
                a1 = __float_as_uint(As[o + 576]);
                a2 = __float_as_uint(As[o + 4]);
                a3 = __float_as_uint(As[o + 580]);
            }
            uint32_t bf[4][2];
            #pragma unroll
            for (int nt = 0; nt < 4; nt++) {
                int o = b_base + ks * 1088 + nt * 8;
                bf[nt][0] = __float_as_uint(Bs[o]);
                bf[nt][1] = __float_as_uint(Bs[o + 544]);
            }
            #pragma unroll
            for (int nt = 0; nt < 4; nt++)
                mma_tf32(acc[nt][0], acc[nt][1], acc[nt][2], acc[nt][3],
                         a0, a1, a2, a3, bf[nt][0], bf[nt][1]);
        }
    }

    __syncthreads();   // reuse pool as xs

    float (*xs)[132] = (float (*)[132])pool;

    // ---- write acc (+b1) into xs ----
    // c0=(g,2t) c1=(g,2t+1) c2=(g+8,2t) c3=(g+8,2t+1) within 16-row half
    {
        int mrow = wm * 16 + g;
        #pragma unroll
        for (int nt = 0; nt < 4; nt++) {
            int n = wn * 32 + nt * 8 + t * 2;
            float2 bb = *(const float2*)(b1 + n);
            xs[mrow][n]         = acc[nt][0] + bb.x;
            xs[mrow][n + 1]     = acc[nt][1] + bb.y;
            xs[mrow + 8][n]     = acc[nt][2] + bb.x;
            xs[mrow + 8][n + 1] = acc[nt][3] + bb.y;
        }
    }
    __syncthreads();

    const int bb_ = m0 >> 9;
    const int l0  = m0 & 511;

    // ---- RoPE + transposed q/k store (32 rows x 32 pairs = 1024 items) ----
    for (int idx = tid; idx < 1024; idx += 256) {
        int p = idx >> 5;     // rope pair
        int i = idx & 31;     // row in tile
        float x0 = xs[i][4 * p + 0];
        float x1 = xs[i][4 * p + 1];
        float x2 = xs[i][4 * p + 2];
        float x3 = xs[i][4 * p + 3];
        float base = exp2f((float)p * -0.41524101186091903f);
        float fr = (float)(l0 + i) * base;
        float s, c;
        sincosf(fr, &s, &c);
        float q0 = x0 * c - x2 * s;
        float q1 = x0 * s + x2 * c;
        float k0 = x1 * c - x3 * s;
        float k1 = x1 * s + x3 * c;
        int d0 = 2 * p;
        g_qwT[(bb_ * HS + d0) * L_ + l0 + i]     = q0;
        g_qwT[(bb_ * HS + d0 + 1) * L_ + l0 + i] = q1;
        g_kwT[(bb_ * HS + d0) * L_ + l0 + i]     = k0;
        g_kwT[(bb_ * HS + d0 + 1) * L_ + l0 + i] = k1;
    }

    // ---- bias = (x@W2 + b2)/2 ----
    if (tid < 192) {
        int jj = tid % 24;
        int r0 = (tid / 24) * 4;
        float accb[4];
        #pragma unroll
        for (int r = 0; r < 4; r++) accb[r] = 0.f;
        for (int cc = 0; cc < 128; cc++) {
            float w = __ldg(&W2[cc * 24 + jj]);
            #pragma unroll
            for (int r = 0; r < 4; r++) accb[r] += xs[r0 + r][cc] * w;
        }
        float bv2 = __ldg(&b2[jj]);
        #pragma unroll
        for (int r = 0; r < 4; r++)
            g_bias[(bb_ * 24 + jj) * L_ + l0 + r0 + r] = (accb[r] + bv2) * 0.5f;
    }
}

// ---------------------------------------------------------------------------
// Kernel B (byte-identical to the R11/R12-passing logits, 38.4us measured).
// ---------------------------------------------------------------------------
__global__ __launch_bounds__(256) void logits_kernel(
    const float* __restrict__ am, float* __restrict__ out)
{
    __shared__ __align__(16) float Qt[64][68];
    __shared__ __align__(16) float Kt[64][68];
    __shared__ float brm[12][64];
    __shared__ float bcn[12][64];
    __shared__ float amm[64], amn[64];

    const int b  = blockIdx.z;
    const int m0 = blockIdx.y * 64;
    const int n0 = blockIdx.x * 64;
    const int tid = threadIdx.x;

    #pragma unroll
    for (int f = tid; f < 1024; f += 256) {
        int d = f >> 4, ig = f & 15;
        *(float4*)&Qt[d][ig * 4] = *(const float4*)&g_qwT[(b * HS + d) * L_ + m0 + ig * 4];
        *(float4*)&Kt[d][ig * 4] = *(const float4*)&g_kwT[(b * HS + d) * L_ + n0 + ig * 4];
    }
    #pragma unroll
    for (int f = tid; f < 768; f += 256) {
        int h = f >> 6, i = f & 63;
        brm[h][i] = g_bias[(b * 24 + 2 * h + 1) * L_ + m0 + i];
        bcn[h][i] = g_bias[(b * 24 + 2 * h) * L_ + n0 + i];
    }
    if (tid < 64)       amm[tid]      = am[b * L_ + m0 + tid];
    else if (tid < 128) amn[tid - 64] = am[b * L_ + n0 + tid - 64];
    __syncthreads();

    const int tx = tid & 15;
    const int ty = tid >> 4;

    float acc[4][4];
    #pragma unroll
    for (int r = 0; r < 4; r++)
        #pragma unroll
        for (int c = 0; c < 4; c++) acc[r][c] = 0.f;

    #pragma unroll 16
    for (int d = 0; d < 64; d++) {
        float4 q = *(float4*)&Qt[d][ty * 4];
        float4 k = *(float4*)&Kt[d][tx * 4];
        float qv[4] = {q.x, q.y, q.z, q.w};
        float kv[4] = {k.x, k.y, k.z, k.w};
        #pragma unroll
        for (int r = 0; r < 4; r++)
            #pragma unroll
            for (int c = 0; c < 4; c++)
                acc[r][c] += qv[r] * kv[c];
    }

    float amr[4], amc[4];
    #pragma unroll
    for (int r = 0; r < 4; r++) amr[r] = amm[ty * 4 + r];
    #pragma unroll
    for (int c = 0; c < 4; c++) amc[c] = amn[tx * 4 + c];
    #pragma unroll
    for (int r = 0; r < 4; r++) {
        int m = m0 + ty * 4 + r;
        #pragma unroll
        for (int c = 0; c < 4; c++) {
            int n = n0 + tx * 4 + c;
            float pen = (1.f - amr[r] * amc[c]) * INFV + ((n < m) ? INFV : 0.f);
            acc[r][c] = acc[r][c] * 0.125f - pen;
        }
    }

    const size_t outbase = (size_t)b * NH * L_ * L_ + (size_t)(m0 + ty * 4) * L_ + n0 + tx * 4;
    #pragma unroll
    for (int h = 0; h < NH; h++) {
        float br[4], bc[4];
        #pragma unroll
        for (int r = 0; r < 4; r++) br[r] = brm[h][ty * 4 + r];
        #pragma unroll
        for (int c = 0; c < 4; c++) bc[c] = bcn[h][tx * 4 + c];
        float* op = out + outbase + (size_t)h * L_ * L_;
        #pragma unroll
        for (int r = 0; r < 4; r++) {
            float4 v;
            v.x = acc[r][0] + br[r] + bc[0];
            v.y = acc[r][1] + br[r] + bc[1];
            v.z = acc[r][2] + br[r] + bc[2];
            v.w = acc[r][3] + br[r] + bc[3];
            *(float4*)(op + (size_t)r * L_) = v;
        }
    }
}

// ---------------------------------------------------------------------------
extern "C" void kernel_launch(void* const* d_in, const int* in_sizes, int n_in,
                              void* d_out, int out_size)
{
    const float* inp = (const float*)d_in[0];  // [16,512,1024]
    const float* am  = (const float*)d_in[1];  // [16,512]
    const float* W1  = (const float*)d_in[2];  // [1024,128]
    const float* b1  = (const float*)d_in[3];  // [128]
    const float* W2  = (const float*)d_in[4];  // [128,24]
    const float* b2  = (const float*)d_in[5];  // [24]
    float* out = (float*)d_out;                // [16,12,512,512]

    proj_kernel<<<256, 256>>>(inp, W1, b1, W2, b2);
    dim3 g(8, 8, 16);
    logits_kernel<<<g, 256>>>(am, out);
}